// round 2
// baseline (speedup 1.0000x reference)
#include <cuda_runtime.h>
#include <math_constants.h>

// Problem constants (KnnEdges: B=4, M=8192, D=2, k=16)
#define B_   4
#define M_   8192
#define N_   (B_ * M_)          // 32768
#define K_   16
#define NE_  (N_ * K_)          // 524288 edges

// Output layout (float32 concat of reference tuple, in return order)
#define OFF_X     0                        // x: N*64 = 2097152
#define OFF_POSP  2097152                  // pos_p: N*2 = 65536
#define OFF_EIDX  2162688                  // edge_index: 2*NE = 1048576 (src row, then tgt row)
#define OFF_EW    3211264                  // edge_weight: NE = 524288
#define OFF_BATCH 3735552                  // batch: N
#define OFF_PERM  3768320                  // perm: N
#define OFF_SCORE 3801088                  // score: N
// total = 3833856

__device__ unsigned g_maxbits;

// ---------------------------------------------------------------------------
// Prep: copy x, gather pos[perm] into out (also consumed by knn kernel),
// write tgt row of edge_index, cast batch/perm, copy score, reset g_maxbits.
// NOTE: batch/perm are int32 on device (JAX x64 disabled downgrades int64).
// ---------------------------------------------------------------------------
__global__ void prep_kernel(const float* __restrict__ x,
                            const float* __restrict__ pos,
                            const int* __restrict__ batch,
                            const int* __restrict__ perm,
                            const float* __restrict__ score,
                            float* __restrict__ out) {
    int t = blockIdx.x * blockDim.x + threadIdx.x;
    if (t == 0) g_maxbits = 0u;

    const int C_X4   = (N_ * 64) / 4;      // 524288 float4 copies of x
    const int C_POSP = N_;                 // 32768 gathers
    const int C_TGT  = NE_;                // 524288 tgt writes

    if (t < C_X4) {
        float4 v = ((const float4*)x)[t];
        ((float4*)(out + OFF_X))[t] = v;
        return;
    }
    t -= C_X4;
    if (t < C_POSP) {
        int p = perm[t];                   // 0 <= p < 65536
        float2 v = ((const float2*)pos)[p];
        out[OFF_POSP + 2 * t]     = v.x;
        out[OFF_POSP + 2 * t + 1] = v.y;
        return;
    }
    t -= C_POSP;
    if (t < C_TGT) {
        out[OFF_EIDX + NE_ + t] = (float)(t >> 4);   // tgt = repeat(arange(N), k)
        return;
    }
    t -= C_TGT;
    if (t < N_) { out[OFF_BATCH + t] = (float)batch[t]; return; }
    t -= N_;
    if (t < N_) { out[OFF_PERM + t] = (float)perm[t]; return; }
    t -= N_;
    if (t < N_) { out[OFF_SCORE + t] = score[t]; return; }
}

// ---------------------------------------------------------------------------
// Brute-force KNN: one thread per target point. Full batch (8192 float2)
// streamed through a 32KB static shared tile (x2 tiles). Sorted-ascending
// top-16 in registers; strict-less insertion in ascending index order
// reproduces jax.lax.top_k stable tie-breaking. d2 uses explicit rn ops
// (no FMA contraction) to bit-match the reference's mul-mul-add.
// ---------------------------------------------------------------------------
__global__ void __launch_bounds__(256) knn_kernel(float* __restrict__ out) {
    __shared__ float2 spos[4096];

    const int b      = blockIdx.x >> 5;        // 32 CTAs per batch
    const int chunk  = blockIdx.x & 31;
    const float2* pp = (const float2*)(out + OFF_POSP) + b * M_;

    const int i_local = chunk * 256 + threadIdx.x;
    const float2 p = pp[i_local];

    float bd[K_];
    int   bi[K_];
#pragma unroll
    for (int t = 0; t < K_; t++) { bd[t] = CUDART_INF_F; bi[t] = 0; }

    for (int tile = 0; tile < 2; tile++) {
        __syncthreads();
        const float4* s4 = (const float4*)(pp + tile * 4096);
        float4* d4 = (float4*)spos;
#pragma unroll
        for (int r = 0; r < 8; r++)
            d4[r * 256 + threadIdx.x] = s4[r * 256 + threadIdx.x];
        __syncthreads();

        const int jbase = tile * 4096;
#pragma unroll 4
        for (int j = 0; j < 4096; j++) {
            float2 q = spos[j];
            float dx = __fsub_rn(p.x, q.x);
            float dy = __fsub_rn(p.y, q.y);
            float d2 = __fadd_rn(__fmul_rn(dx, dx), __fmul_rn(dy, dy));
            if (d2 < bd[K_ - 1]) {
                bd[K_ - 1] = d2;
                bi[K_ - 1] = jbase + j;
#pragma unroll
                for (int t = K_ - 1; t > 0; t--) {
                    if (bd[t] < bd[t - 1]) {
                        float td = bd[t]; bd[t] = bd[t - 1]; bd[t - 1] = td;
                        int   ti = bi[t]; bi[t] = bi[t - 1]; bi[t - 1] = ti;
                    }
                }
            }
        }
    }

    const int tgt = b * M_ + i_local;
    float lmax = 0.0f;
#pragma unroll
    for (int t = 0; t < K_; t++) {
        out[OFF_EIDX + tgt * K_ + t] = (float)(b * M_ + bi[t]);
        float dist = __fsqrt_rn(bd[t]);           // d2 >= 0 always
        out[OFF_EW + tgt * K_ + t] = dist;
        lmax = fmaxf(lmax, dist);
    }
    atomicMax(&g_maxbits, __float_as_uint(lmax)); // positive floats: uint order == float order
}

// ---------------------------------------------------------------------------
// Normalize edge weights by global max distance.
// ---------------------------------------------------------------------------
__global__ void norm_kernel(float* __restrict__ out) {
    int t = blockIdx.x * blockDim.x + threadIdx.x;
    float m = __uint_as_float(g_maxbits);
    out[OFF_EW + t] = out[OFF_EW + t] / m;
}

extern "C" void kernel_launch(void* const* d_in, const int* in_sizes, int n_in,
                              void* d_out, int out_size) {
    const float* x     = (const float*)d_in[0];
    const float* pos   = (const float*)d_in[1];
    // d_in[2] edge_index, d_in[3] edge_weight: unused by reference outputs
    const int*   batch = (const int*)d_in[4];
    const int*   perm  = (const int*)d_in[5];
    const float* score = (const float*)d_in[6];
    float* out = (float*)d_out;

    // prep: 524288 + 32768 + 524288 + 3*32768 = 1179648 threads
    const int prep_threads = (N_ * 64) / 4 + N_ + NE_ + 3 * N_;
    prep_kernel<<<(prep_threads + 255) / 256, 256>>>(x, pos, batch, perm, score, out);

    knn_kernel<<<B_ * (M_ / 256), 256>>>(out);

    norm_kernel<<<NE_ / 256, 256>>>(out);
}

// round 3
// speedup vs baseline: 5.6955x; 5.6955x over previous
#include <cuda_runtime.h>
#include <math_constants.h>

// Problem constants (KnnEdges: B=4, M=8192, D=2, k=16)
#define B_   4
#define M_   8192
#define N_   (B_ * M_)          // 32768
#define K_   16
#define NE_  (N_ * K_)          // 524288

// Spatial grid: cell = 16.0 (power of two -> exact binning/bounds), 63x63 cells
#define G_    63
#define GG_   (G_ * G_)         // 3969
#define INVH_ 0.0625f

// Output layout (float32 concat of reference tuple)
#define OFF_X     0
#define OFF_POSP  2097152
#define OFF_EIDX  2162688
#define OFF_EW    3211264
#define OFF_BATCH 3735552
#define OFF_PERM  3768320
#define OFF_SCORE 3801088

__device__ int      g_cnt[B_][GG_ + 1];   // counts -> exclusive starts; [GG_] = M
__device__ int      g_ptr[B_][GG_];       // scatter cursors
__device__ float4   g_pts[N_];            // grid-sorted (x, y, idx_bits, 0)
__device__ unsigned g_maxbits;

__device__ __forceinline__ int cell_of(float v) {
    int c = (int)(v * INVH_);
    return c > G_ - 1 ? G_ - 1 : (c < 0 ? 0 : c);
}

// ---------------------------------------------------------------------------
__global__ void zero_kernel() {
    int t = blockIdx.x * blockDim.x + threadIdx.x;
    if (t == 0) g_maxbits = 0u;
    if (t < B_ * (GG_ + 1)) ((int*)g_cnt)[t] = 0;
}

// ---------------------------------------------------------------------------
// Copies/casts/gather + grid cell counting. batch/perm are int32 on device.
// ---------------------------------------------------------------------------
__global__ void prep_kernel(const float* __restrict__ x,
                            const float* __restrict__ pos,
                            const int* __restrict__ batch,
                            const int* __restrict__ perm,
                            const float* __restrict__ score,
                            float* __restrict__ out) {
    int t = blockIdx.x * blockDim.x + threadIdx.x;

    const int C_X4 = (N_ * 64) / 4;
    if (t < C_X4) {
        ((float4*)(out + OFF_X))[t] = ((const float4*)x)[t];
        return;
    }
    t -= C_X4;
    if (t < N_) {
        int p = perm[t];
        float2 v = ((const float2*)pos)[p];
        out[OFF_POSP + 2 * t]     = v.x;
        out[OFF_POSP + 2 * t + 1] = v.y;
        int b = t >> 13;
        atomicAdd(&g_cnt[b][cell_of(v.y) * G_ + cell_of(v.x)], 1);
        return;
    }
    t -= N_;
    if (t < NE_) { out[OFF_EIDX + NE_ + t] = (float)(t >> 4); return; }
    t -= NE_;
    if (t < N_) { out[OFF_BATCH + t] = (float)batch[t]; return; }
    t -= N_;
    if (t < N_) { out[OFF_PERM + t] = (float)perm[t]; return; }
    t -= N_;
    if (t < N_) { out[OFF_SCORE + t] = score[t]; return; }
}

// ---------------------------------------------------------------------------
// Per-batch exclusive prefix sum over GG_ cell counts (one CTA per batch).
// ---------------------------------------------------------------------------
__global__ void __launch_bounds__(1024) scan_kernel() {
    __shared__ int sh[1024];
    const int b = blockIdx.x;
    const int t = threadIdx.x;
    const int base = t * 4;

    int v[4], tot = 0;
#pragma unroll
    for (int i = 0; i < 4; i++) {
        v[i] = (base + i < GG_) ? g_cnt[b][base + i] : 0;
        tot += v[i];
    }
    sh[t] = tot;
    __syncthreads();
    for (int off = 1; off < 1024; off <<= 1) {
        int u = (t >= off) ? sh[t - off] : 0;
        __syncthreads();
        sh[t] += u;
        __syncthreads();
    }
    int run = sh[t] - tot;   // exclusive
#pragma unroll
    for (int i = 0; i < 4; i++) {
        if (base + i < GG_) { g_cnt[b][base + i] = run; g_ptr[b][base + i] = run; }
        run += v[i];
    }
    if (t == 1023) g_cnt[b][GG_] = run;   // = M_
}

// ---------------------------------------------------------------------------
// Scatter points into grid-sorted order (payload keeps original local index).
// ---------------------------------------------------------------------------
__global__ void scatter_kernel(const float* __restrict__ out) {
    int t = blockIdx.x * blockDim.x + threadIdx.x;
    if (t >= N_) return;
    int b = t >> 13, i = t & (M_ - 1);
    float px = out[OFF_POSP + 2 * t];
    float py = out[OFF_POSP + 2 * t + 1];
    int c = cell_of(py) * G_ + cell_of(px);
    int dst = atomicAdd(&g_ptr[b][c], 1);
    g_pts[b * M_ + dst] = make_float4(px, py, __int_as_float(i), 0.0f);
}

// ---------------------------------------------------------------------------
// Exact KNN via expanding-ring grid search. Top-16 by lexicographic (d2, idx)
// == jax.lax.top_k(-d2) output (ascending d2, ties by smaller index).
// d2 uses explicit rn ops (no FMA) to bit-match XLA's sub/mul/mul/add.
// Stop bound: unvisited ring >= r implies d2 >= ((r-1)*16)^2 (exact fp).
// ---------------------------------------------------------------------------
__global__ void __launch_bounds__(256) knn_kernel(float* __restrict__ out) {
    int t = blockIdx.x * 256 + threadIdx.x;
    int b = t >> 13, s = t & (M_ - 1);

    const float4* __restrict__ pts = g_pts + b * M_;
    const int*    __restrict__ cs  = g_cnt[b];

    float4 q = pts[s];
    int qi = __float_as_int(q.z);
    int cx = cell_of(q.x), cy = cell_of(q.y);

    float bd[K_];
    int   bi[K_];
#pragma unroll
    for (int u = 0; u < K_; u++) { bd[u] = CUDART_INF_F; bi[u] = 0x7fffffff; }

#define PROCESS_CELL(XX, YY)                                                   \
    {                                                                          \
        int c_ = (YY) * G_ + (XX);                                             \
        int js_ = cs[c_], je_ = cs[c_ + 1];                                    \
        for (int j_ = js_; j_ < je_; j_++) {                                   \
            float4 v_ = pts[j_];                                               \
            float dx_ = __fsub_rn(q.x, v_.x);                                  \
            float dy_ = __fsub_rn(q.y, v_.y);                                  \
            float d2_ = __fadd_rn(__fmul_rn(dx_, dx_), __fmul_rn(dy_, dy_));   \
            int vi_ = __float_as_int(v_.z);                                    \
            if (d2_ < bd[K_ - 1] || (d2_ == bd[K_ - 1] && vi_ < bi[K_ - 1])) { \
                bd[K_ - 1] = d2_; bi[K_ - 1] = vi_;                            \
                _Pragma("unroll")                                              \
                for (int u_ = K_ - 1; u_ > 0; u_--) {                          \
                    bool sw_ = bd[u_] < bd[u_ - 1] ||                          \
                               (bd[u_] == bd[u_ - 1] && bi[u_] < bi[u_ - 1]);  \
                    if (sw_) {                                                 \
                        float td_ = bd[u_]; bd[u_] = bd[u_ - 1]; bd[u_ - 1] = td_; \
                        int ti_ = bi[u_]; bi[u_] = bi[u_ - 1]; bi[u_ - 1] = ti_;   \
                    }                                                          \
                }                                                              \
            }                                                                  \
        }                                                                      \
    }

    for (int r = 0; r < G_; r++) {
        if (r >= 2) {
            float bound = (float)(r - 1) * 16.0f;          // exact
            if (bd[K_ - 1] < bound * bound) break;         // strict: ties safe
        }
        int x0 = cx - r, x1 = cx + r, y0 = cy - r, y1 = cy + r;
        int xa = x0 < 0 ? 0 : x0, xb = x1 > G_ - 1 ? G_ - 1 : x1;
        int ya = y0 < 0 ? 0 : y0, yb = y1 > G_ - 1 ? G_ - 1 : y1;
        for (int yy = ya; yy <= yb; yy++) {
            if (yy == y0 || yy == y1) {
                for (int xx = xa; xx <= xb; xx++) PROCESS_CELL(xx, yy);
            } else {
                if (x0 >= 0)      PROCESS_CELL(x0, yy);
                if (x1 <= G_ - 1) PROCESS_CELL(x1, yy);
            }
        }
    }
#undef PROCESS_CELL

    const int tgt = b * M_ + qi;
    float lmax = 0.0f;
#pragma unroll
    for (int u = 0; u < K_; u++) {
        out[OFF_EIDX + tgt * K_ + u] = (float)(b * M_ + bi[u]);
        float dist = __fsqrt_rn(bd[u]);
        out[OFF_EW + tgt * K_ + u] = dist;
        lmax = fmaxf(lmax, dist);
    }
#pragma unroll
    for (int o = 16; o; o >>= 1)
        lmax = fmaxf(lmax, __shfl_xor_sync(0xffffffffu, lmax, o));
    if ((threadIdx.x & 31) == 0)
        atomicMax(&g_maxbits, __float_as_uint(lmax));
}

// ---------------------------------------------------------------------------
__global__ void norm_kernel(float* __restrict__ out) {
    int t = blockIdx.x * blockDim.x + threadIdx.x;
    float m = __uint_as_float(g_maxbits);
    out[OFF_EW + t] = out[OFF_EW + t] / m;
}

extern "C" void kernel_launch(void* const* d_in, const int* in_sizes, int n_in,
                              void* d_out, int out_size) {
    const float* x     = (const float*)d_in[0];
    const float* pos   = (const float*)d_in[1];
    const int*   batch = (const int*)d_in[4];
    const int*   perm  = (const int*)d_in[5];
    const float* score = (const float*)d_in[6];
    float* out = (float*)d_out;

    zero_kernel<<<(B_ * (GG_ + 1) + 255) / 256, 256>>>();

    const int prep_threads = (N_ * 64) / 4 + N_ + NE_ + 3 * N_;
    prep_kernel<<<(prep_threads + 255) / 256, 256>>>(x, pos, batch, perm, score, out);

    scan_kernel<<<B_, 1024>>>();
    scatter_kernel<<<(N_ + 255) / 256, 256>>>(out);
    knn_kernel<<<N_ / 256, 256>>>(out);
    norm_kernel<<<NE_ / 256, 256>>>(out);
}